// round 1
// baseline (speedup 1.0000x reference)
#include <cuda_runtime.h>
#include <math.h>

#define B_   128
#define L_   512
#define NH   1024
#define DTc  0.05f

// per-block partial stats: [thrf, tlif, vs, vsq, ls, lsq, pad, pad]
__device__ float g_partials[B_ * 8];

__device__ __forceinline__ float fadd(float a, float b){ return __fadd_rn(a,b); }
__device__ __forceinline__ float fmul(float a, float b){ return __fmul_rn(a,b); }
__device__ __forceinline__ float fsub(float a, float b){ return __fsub_rn(a,b); }

__device__ __forceinline__ float block_reduce(float v, int wid, int lane, float* redf)
{
    #pragma unroll
    for (int o = 16; o > 0; o >>= 1) v += __shfl_down_sync(0xffffffffu, v, o);
    if (lane == 0) redf[wid] = v;
    __syncthreads();
    float r = 0.f;
    if (wid == 0) {
        r = redf[lane];
        #pragma unroll
        for (int o = 16; o > 0; o >>= 1) r += __shfl_down_sync(0xffffffffu, r, o);
    }
    __syncthreads();
    return r;   // valid on (wid==0, lane==0)
}

__global__ __launch_bounds__(1024, 1) void coesn_kernel(
    const float* __restrict__ x,        // (B, L, 1)
    const float* __restrict__ x2h,      // (1, NH)
    const float* __restrict__ h2h,      // (NH, NH) row-major [k][j]
    const float* __restrict__ bias,     // (NH)
    const float* __restrict__ lif2hrf,  // (NH, NH)
    const float* __restrict__ gamma,    // (NH)
    const float* __restrict__ eps,      // (NH)
    const float* __restrict__ sgain,    // scalar
    float* __restrict__ out)            // (B*NH hy) ++ 7 scalars
{
    const int b    = blockIdx.x;
    const int j    = threadIdx.x;
    const int wid  = j >> 5;
    const int lane = j & 31;
    const unsigned lmask_lt = (1u << lane) - 1u;

    __shared__ float          xs[L_];
    __shared__ unsigned short list_s[NH];   // HRF spike indices (consumed next step)
    __shared__ unsigned short list_l[NH];   // LIF spike indices (consumed same step)
    __shared__ int            wcnt[32];
    __shared__ float          redf[32];

    if (j < L_) xs[j] = x[b * L_ + j];

    const float rw = x2h[j];
    const float rb = bias[j];
    const float rg = gamma[j];
    const float re = eps[j];
    const float rs = sgain[0];
    const float refd = 0.81873075307798182f;   // exp(-DT/TAU_REF) = exp(-0.2)

    float hy = 0.f, hz = 0.f, ref = 0.f, v = 0.f;
    float vs = 0.f, vsq = 0.f, ls = 0.f, lsq = 0.f;
    int thrf = 0, tlif = 0;
    int s_cnt = 0;

    const float* hp = h2h + j;
    const float* lp = lif2hrf + j;

    __syncthreads();

    for (int t = 0; t < L_; t++) {
        const float xt = xs[t];

        // ---------- phase 1: cur = x*x2h + s@h2h + bias ; LIF update ----------
        float a0 = 0.f, a1 = 0.f, a2 = 0.f, a3 = 0.f;
        int i = 0;
        for (; i + 4 <= s_cnt; i += 4) {
            int k0 = list_s[i], k1 = list_s[i+1], k2 = list_s[i+2], k3 = list_s[i+3];
            a0 += __ldg(hp + k0 * NH);
            a1 += __ldg(hp + k1 * NH);
            a2 += __ldg(hp + k2 * NH);
            a3 += __ldg(hp + k3 * NH);
        }
        for (; i < s_cnt; i++) a0 += __ldg(hp + ((int)list_s[i]) * NH);
        float gem = fadd(fadd(a0, a1), fadd(a2, a3));
        float cur = fadd(fadd(fmul(xt, rw), gem), rb);

        v = fadd(v, fmul(DTc, fadd(__fdiv_rn(-v, 20.0f), cur)));
        bool lspk = (v > 1.0f);
        if (lspk) v = fsub(v, 1.0f);
        tlif += lspk ? 1 : 0;
        vs  = fadd(vs, v);
        vsq = fadd(vsq, fmul(v, v));

        // ---------- build LIF active list (sorted, deterministic) ----------
        unsigned m = __ballot_sync(0xffffffffu, lspk);
        if (lane == 0) wcnt[wid] = __popc(m);
        __syncthreads();
        int cw = wcnt[lane];
        #pragma unroll
        for (int o = 1; o < 32; o <<= 1) {
            int n = __shfl_up_sync(0xffffffffu, cw, o);
            if (lane >= o) cw += n;
        }
        int tot  = __shfl_sync(0xffffffffu, cw, 31);
        int base = __shfl_sync(0xffffffffu, cw, (wid == 0) ? 0 : wid - 1);
        if (wid == 0) base = 0;
        if (lspk) list_l[base + __popc(m & lmask_lt)] = (unsigned short)j;
        __syncthreads();

        // ---------- phase 2: l2h = lif_s @ lif2hrf ; HRF update ----------
        a0 = a1 = a2 = a3 = 0.f; i = 0;
        for (; i + 4 <= tot; i += 4) {
            int k0 = list_l[i], k1 = list_l[i+1], k2 = list_l[i+2], k3 = list_l[i+3];
            a0 += __ldg(lp + k0 * NH);
            a1 += __ldg(lp + k1 * NH);
            a2 += __ldg(lp + k2 * NH);
            a3 += __ldg(lp + k3 * NH);
        }
        for (; i < tot; i++) a0 += __ldg(lp + ((int)list_l[i]) * NH);
        float l2h = fadd(fadd(a0, a1), fadd(a2, a3));

        ls  = fadd(ls, l2h);
        lsq = fadd(lsq, fmul(l2h, l2h));

        float dd = fsub(fsub(fmul(rs, l2h), fmul(rg, hy)), fmul(re, hz));
        hz = fadd(hz, fmul(DTc, dd));
        hy = fadd(hy, fmul(DTc, hz));
        bool spk = (fsub(fsub(hy, 1.0f), ref) > 0.0f);
        ref = fadd(fmul(ref, refd), spk ? 1.0f : 0.0f);
        thrf += spk ? 1 : 0;

        // ---------- build HRF active list for next step ----------
        m = __ballot_sync(0xffffffffu, spk);
        if (lane == 0) wcnt[wid] = __popc(m);
        __syncthreads();
        cw = wcnt[lane];
        #pragma unroll
        for (int o = 1; o < 32; o <<= 1) {
            int n = __shfl_up_sync(0xffffffffu, cw, o);
            if (lane >= o) cw += n;
        }
        s_cnt = __shfl_sync(0xffffffffu, cw, 31);
        base  = __shfl_sync(0xffffffffu, cw, (wid == 0) ? 0 : wid - 1);
        if (wid == 0) base = 0;
        if (spk) list_s[base + __popc(m & lmask_lt)] = (unsigned short)j;
        __syncthreads();
    }

    out[b * NH + j] = hy;

    // ---------- block-level stat reductions (deterministic trees) ----------
    float r;
    r = block_reduce((float)thrf, wid, lane, redf); if (j == 0) g_partials[b*8 + 0] = r;
    r = block_reduce((float)tlif, wid, lane, redf); if (j == 0) g_partials[b*8 + 1] = r;
    r = block_reduce(vs,  wid, lane, redf);         if (j == 0) g_partials[b*8 + 2] = r;
    r = block_reduce(vsq, wid, lane, redf);         if (j == 0) g_partials[b*8 + 3] = r;
    r = block_reduce(ls,  wid, lane, redf);         if (j == 0) g_partials[b*8 + 4] = r;
    r = block_reduce(lsq, wid, lane, redf);         if (j == 0) g_partials[b*8 + 5] = r;
}

__global__ void finalize_kernel(float* __restrict__ out)
{
    if (threadIdx.x != 0 || blockIdx.x != 0) return;
    double th = 0, tl = 0, vs = 0, vsq = 0, ls = 0, lsq = 0;
    for (int b = 0; b < B_; b++) {
        th  += (double)g_partials[b*8 + 0];
        tl  += (double)g_partials[b*8 + 1];
        vs  += (double)g_partials[b*8 + 2];
        vsq += (double)g_partials[b*8 + 3];
        ls  += (double)g_partials[b*8 + 4];
        lsq += (double)g_partials[b*8 + 5];
    }
    const double denom = (double)B_ * (double)L_ * (double)NH;
    float r_hrf = (float)(th / denom);
    float r_lif = (float)(tl / denom);
    float vm    = (float)(vs / denom);
    float vstd  = sqrtf((float)(vsq / denom) - vm * vm);
    float lm    = (float)(ls / denom);
    float lstd  = sqrtf((float)(lsq / denom) - lm * lm);
    float* sc = out + B_ * NH;
    sc[0] = r_hrf;   // r_total (count_lif_spikes=False)
    sc[1] = r_hrf;
    sc[2] = r_lif;
    sc[3] = vm;
    sc[4] = vstd;
    sc[5] = lm;
    sc[6] = lstd;
}

extern "C" void kernel_launch(void* const* d_in, const int* in_sizes, int n_in,
                              void* d_out, int out_size)
{
    const float* x       = (const float*)d_in[0];
    const float* x2h     = (const float*)d_in[1];
    const float* h2h     = (const float*)d_in[2];
    const float* bias    = (const float*)d_in[3];
    const float* lif2hrf = (const float*)d_in[4];
    const float* gamma   = (const float*)d_in[5];
    const float* eps     = (const float*)d_in[6];
    const float* sg      = (const float*)d_in[7];
    float* out = (float*)d_out;

    coesn_kernel<<<B_, 1024>>>(x, x2h, h2h, bias, lif2hrf, gamma, eps, sg, out);
    finalize_kernel<<<1, 32>>>(out);
}